// round 8
// baseline (speedup 1.0000x reference)
#include <cuda_runtime.h>
#include <cuda_bf16.h>
#include <cstdint>

#define NN 100000
#define EE 1280000
#define RR 8
#define DD 64
#define TT 50000
#define RN (RR * NN)                       // 800000 CSR keys
#define S2_BLKS ((RN + 1023) / 1024)       // 782

// ---- scratch (device globals: alloc-free rule) ----
__device__ float g_x[(size_t)NN * DD];
__device__ float g_x2[(size_t)NN * DD];
__device__ float g_invdeg[NN];
__device__ __nv_bfloat16 g_wh[2 * RR * DD * DD];  // W^T hi  [l][r][n][k]
__device__ __nv_bfloat16 g_wl[2 * RR * DD * DD];
__device__ __nv_bfloat16 g_rh[2 * DD * DD];       // root^T hi [l][n][k]
__device__ __nv_bfloat16 g_rl[2 * DD * DD];
// CSR keyed by g = r*NN + dst
__device__ int g_hist2[RN];
__device__ int g_rs2[RN + 1];
__device__ int g_cur2[RN];
__device__ int g_bsum2[S2_BLKS];
__device__ int g_boff2[S2_BLKS];
__device__ uint32_t g_eg[EE];   // packed: src(20b) | dlocal(7b)<<20

__device__ __forceinline__ uint32_t smem_u32(const void* p) {
    uint32_t a;
    asm("{ .reg .u64 t; cvta.to.shared.u64 t, %1; cvt.u32.u64 %0, t; }" : "=r"(a) : "l"(p));
    return a;
}

#define LDM_X4(r, addr)                                                          \
    asm volatile("ldmatrix.sync.aligned.m8n8.x4.shared.b16 {%0,%1,%2,%3}, [%4];" \
        : "=r"((r)[0]), "=r"((r)[1]), "=r"((r)[2]), "=r"((r)[3]) : "r"(addr))

#define LDM_X2(r, addr)                                                          \
    asm volatile("ldmatrix.sync.aligned.m8n8.x2.shared.b16 {%0,%1}, [%2];"       \
        : "=r"((r)[0]), "=r"((r)[1]) : "r"(addr))

#define MMA_BF16(c, a, b)                                                        \
    asm volatile("mma.sync.aligned.m16n8k16.row.col.f32.bf16.bf16.f32 "          \
        "{%0,%1,%2,%3}, {%4,%5,%6,%7}, {%8,%9}, {%0,%1,%2,%3};"                  \
        : "+f"((c)[0]), "+f"((c)[1]), "+f"((c)[2]), "+f"((c)[3])                 \
        : "r"((a)[0]), "r"((a)[1]), "r"((a)[2]), "r"((a)[3]),                    \
          "r"((b)[0]), "r"((b)[1]))

__device__ __forceinline__ void split_store(float v, __nv_bfloat16* hi, __nv_bfloat16* lo) {
    __nv_bfloat16 h = __float2bfloat16(v);
    *hi = h;
    *lo = __float2bfloat16(v - __bfloat162float(h));
}

// ---- init: x = node_emb[x_idx] ----
__global__ void k_init_x(const int* __restrict__ x_idx, const float* __restrict__ emb) {
    int i = blockIdx.x * blockDim.x + threadIdx.x;
    if (i >= NN * (DD / 4)) return;
    int n = i >> 4, c = i & 15;
    int s = x_idx[n];
    reinterpret_cast<float4*>(g_x)[(size_t)n * 16 + c] =
        reinterpret_cast<const float4*>(emb)[(size_t)s * 16 + c];
}

// ---- prep: transpose + split W (both layers) and root ----
__global__ void k_prep_w(const float* __restrict__ W, const float* __restrict__ root) {
    int idx = blockIdx.x * blockDim.x + threadIdx.x;
    int nW = 2 * RR * DD * DD;
    if (idx < nW) {
        int k = idx & 63, n = (idx >> 6) & 63, r = (idx >> 12) & 7, l = idx >> 15;
        float v = W[(((size_t)l * RR + r) * DD + k) * DD + n];
        split_store(v, &g_wh[idx], &g_wl[idx]);
    } else if (idx < nW + 2 * DD * DD) {
        int o = idx - nW;
        int k = o & 63, n = (o >> 6) & 63, l = o >> 12;
        float v = root[((size_t)l * DD + k) * DD + n];
        split_store(v, &g_rh[o], &g_rl[o]);
    }
}

// ---- CSR build over keys g = r*NN + dst ----
__global__ void k_hist2(const int* __restrict__ ei, const int* __restrict__ et) {
    int e = blockIdx.x * blockDim.x + threadIdx.x;
    if (e < EE) atomicAdd(&g_hist2[et[e] * NN + ei[EE + e]], 1);
}

__global__ __launch_bounds__(1024) void k_scan1() {
    __shared__ int sh[1024];
    int tid = threadIdx.x;
    int i = blockIdx.x * 1024 + tid;
    int v = (i < RN) ? g_hist2[i] : 0;
    sh[tid] = v;
    __syncthreads();
    for (int off = 1; off < 1024; off <<= 1) {
        int t = (tid >= off) ? sh[tid - off] : 0;
        __syncthreads();
        sh[tid] += t;
        __syncthreads();
    }
    if (i < RN) g_rs2[i] = sh[tid] - v;
    if (tid == 1023) g_bsum2[blockIdx.x] = sh[1023];
}

__global__ __launch_bounds__(1024) void k_scan2() {
    __shared__ int sh[1024];
    int tid = threadIdx.x;
    int v = (tid < S2_BLKS) ? g_bsum2[tid] : 0;
    sh[tid] = v;
    __syncthreads();
    for (int off = 1; off < 1024; off <<= 1) {
        int t = (tid >= off) ? sh[tid - off] : 0;
        __syncthreads();
        sh[tid] += t;
        __syncthreads();
    }
    if (tid < S2_BLKS) g_boff2[tid] = sh[tid] - v;
}

__global__ __launch_bounds__(1024) void k_scan3() {
    int i = blockIdx.x * 1024 + threadIdx.x;
    if (i < RN) {
        int rs = g_rs2[i] + g_boff2[blockIdx.x];
        g_rs2[i] = rs;
        g_cur2[i] = rs;
    }
    if (i == 0) g_rs2[RN] = EE;
}

// ---- invdeg from hist2 ----
__global__ void k_invdeg2() {
    int n = blockIdx.x * blockDim.x + threadIdx.x;
    if (n >= NN) return;
    int deg = 0;
#pragma unroll
    for (int r = 0; r < RR; r++) deg += g_hist2[r * NN + n];
    g_invdeg[n] = 1.0f / fmaxf((float)deg, 1.0f);
}

__global__ void k_scatter2(const int* __restrict__ ei, const int* __restrict__ et) {
    int e = blockIdx.x * blockDim.x + threadIdx.x;
    if (e >= EE) return;
    int dst = ei[EE + e];
    int key = et[e] * NN + dst;
    int pos = atomicAdd(&g_cur2[key], 1);
    g_eg[pos] = (uint32_t)ei[e] | ((uint32_t)(dst & 127) << 20);
}

// ================= fused layer kernel =================
// Block: 256 threads, 128 dst nodes. For r=0..7: S = sum of x[src] over (r,dst)
// edges (smem fp32 atomics); r=8: S = x[dst] (root). Convert S (*invdeg for r<8)
// to bf16 hi/lo split, HMMA-accumulate against W[r]^T split. Epilogue: +bias, relu.
#define SM_S  0                    // fp32 [128][72]  36864 B
#define SM_SH 36864                // bf16 [128][72]  18432 B
#define SM_SL 55296                // bf16 [128][72]  18432 B
#define SM_WH2 73728               // bf16 [64][72]    9216 B
#define SM_WL2 82944               // bf16 [64][72]    9216 B
#define SM2_TOTAL 92160

__device__ __forceinline__ void load_w_tile(char* sm, int tid,
                                            const __nv_bfloat16* sH,
                                            const __nv_bfloat16* sL) {
    for (int i = tid; i < 64 * 8; i += 256) {
        int row = i >> 3, c = i & 7;
        *reinterpret_cast<uint4*>(sm + SM_WH2 + row * 144 + c * 16) =
            reinterpret_cast<const uint4*>(sH)[row * 8 + c];
        *reinterpret_cast<uint4*>(sm + SM_WL2 + row * 144 + c * 16) =
            reinterpret_cast<const uint4*>(sL)[row * 8 + c];
    }
}

__device__ __forceinline__ void gather_rel(float* S, const float* __restrict__ xin,
                                           int r, int n0, int wid, int lane) {
    int hi = r * NN + ((n0 + 128 < NN) ? n0 + 128 : NN);
    int beg = g_rs2[r * NN + n0];
    int end = g_rs2[hi];
    int e = beg + wid;
    for (; e + 8 < end; e += 16) {
        uint32_t p0 = g_eg[e], p1 = g_eg[e + 8];
        int s0 = p0 & 0xFFFFF, d0 = p0 >> 20;
        int s1 = p1 & 0xFFFFF, d1 = p1 >> 20;
        float a0 = xin[(size_t)s0 * DD + lane];
        float b0 = xin[(size_t)s0 * DD + 32 + lane];
        float a1 = xin[(size_t)s1 * DD + lane];
        float b1 = xin[(size_t)s1 * DD + 32 + lane];
        atomicAdd(&S[d0 * 72 + lane], a0);
        atomicAdd(&S[d0 * 72 + 32 + lane], b0);
        atomicAdd(&S[d1 * 72 + lane], a1);
        atomicAdd(&S[d1 * 72 + 32 + lane], b1);
    }
    if (e < end) {
        uint32_t p = g_eg[e];
        int s0 = p & 0xFFFFF, d0 = p >> 20;
        float a0 = xin[(size_t)s0 * DD + lane];
        float b0 = xin[(size_t)s0 * DD + 32 + lane];
        atomicAdd(&S[d0 * 72 + lane], a0);
        atomicAdd(&S[d0 * 72 + 32 + lane], b0);
    }
}

__global__ __launch_bounds__(256)
void k_layer(const float* __restrict__ xin, float* __restrict__ xout,
             const __nv_bfloat16* __restrict__ wh, const __nv_bfloat16* __restrict__ wl,
             const __nv_bfloat16* __restrict__ rh, const __nv_bfloat16* __restrict__ rl,
             const float* __restrict__ bias) {
    extern __shared__ __align__(16) char sm[];
    float* S = reinterpret_cast<float*>(sm + SM_S);
    int tid = threadIdx.x, wid = tid >> 5, lane = tid & 31;
    int n0 = blockIdx.x * 128;

    // zero S
    for (int i = tid; i < 128 * 72 / 2; i += 256)
        reinterpret_cast<float2*>(S)[i] = make_float2(0.f, 0.f);
    __syncthreads();

    gather_rel(S, xin, 0, n0, wid, lane);
    load_w_tile(sm, tid, wh, wl);

    float acc[8][4] = {};
    uint32_t sb = smem_u32(sm);
    uint32_t a_row = wid * 16 + (lane & 15);
    uint32_t a_col_half = (lane >> 4);
    int tt = lane & 15;
    uint32_t b_row = tt & 7;
    uint32_t b_half = (tt >> 3) & 1;

    for (int r = 0; r <= 8; r++) {
        __syncthreads();   // gather(r) + W(r) complete

        // convert S -> bf16 split (scaled by invdeg for r<8), re-zero S
        for (int i = tid; i < 128 * 32; i += 256) {
            int row = i >> 5, c2 = i & 31;
            float2 v;
            if (r < 8) {
                float* sp = &S[row * 72 + c2 * 2];
                v = *reinterpret_cast<float2*>(sp);
                int n = n0 + row;
                float id = g_invdeg[(n < NN) ? n : (NN - 1)];
                v.x *= id; v.y *= id;
                *reinterpret_cast<float2*>(sp) = make_float2(0.f, 0.f);
            } else {
                int n = n0 + row;
                v = (n < NN) ? *reinterpret_cast<const float2*>(&xin[(size_t)n * DD + c2 * 2])
                             : make_float2(0.f, 0.f);
            }
            __nv_bfloat16 hx = __float2bfloat16(v.x);
            __nv_bfloat16 hy = __float2bfloat16(v.y);
            __nv_bfloat162 hh;  hh.x = hx;  hh.y = hy;
            __nv_bfloat162 ll;
            ll.x = __float2bfloat16(v.x - __bfloat162float(hx));
            ll.y = __float2bfloat16(v.y - __bfloat162float(hy));
            *reinterpret_cast<__nv_bfloat162*>(sm + SM_SH + (row * 72 + c2 * 2) * 2) = hh;
            *reinterpret_cast<__nv_bfloat162*>(sm + SM_SL + (row * 72 + c2 * 2) * 2) = ll;
        }
        __syncthreads();   // Sh/Sl ready, S zeroed

        // MMA accumulate: acc += Sh@Wh + Sh@Wl + Sl@Wh
#pragma unroll
        for (int kb = 0; kb < 4; kb++) {
            uint32_t aoff = a_row * 144 + (kb * 16 + a_col_half * 8) * 2;
            uint32_t ah[4], al[4];
            LDM_X4(ah, sb + SM_SH + aoff);
            LDM_X4(al, sb + SM_SL + aoff);
#pragma unroll
            for (int nb = 0; nb < 8; nb++) {
                uint32_t boff = (nb * 8 + b_row) * 144 + (kb * 16 + b_half * 8) * 2;
                uint32_t bh[2], bl[2];
                LDM_X2(bh, sb + SM_WH2 + boff);
                LDM_X2(bl, sb + SM_WL2 + boff);
                MMA_BF16(acc[nb], ah, bh);
                MMA_BF16(acc[nb], ah, bl);
                MMA_BF16(acc[nb], al, bh);
            }
        }
        __syncthreads();   // all warps done with W smem

        if (r < 8) {
            if (r + 1 < 8) gather_rel(S, xin, r + 1, n0, wid, lane);
            const __nv_bfloat16* nH = (r + 1 < 8) ? wh + (r + 1) * DD * DD : rh;
            const __nv_bfloat16* nL = (r + 1 < 8) ? wl + (r + 1) * DD * DD : rl;
            load_w_tile(sm, tid, nH, nL);
        }
    }

    // epilogue: acc + bias, relu -> xout
    int row0 = n0 + wid * 16 + (lane >> 2);
    int col2 = (lane & 3) * 2;
#pragma unroll
    for (int nb = 0; nb < 8; nb++) {
        int col = nb * 8 + col2;
        float2 bs = *reinterpret_cast<const float2*>(bias + col);
#pragma unroll
        for (int rr2 = 0; rr2 < 2; rr2++) {
            int row = row0 + rr2 * 8;
            if (row < NN) {
                float ox = fmaxf(acc[nb][rr2 * 2 + 0] + bs.x, 0.f);
                float oy = fmaxf(acc[nb][rr2 * 2 + 1] + bs.y, 0.f);
                *reinterpret_cast<float2*>(xout + (size_t)row * DD + col) =
                    make_float2(ox, oy);
            }
        }
    }
}

// ---- final: out[t] = dot(x[s_t], x[t_t]) ; warp per target ----
__global__ void k_score(const int* __restrict__ tei, float* __restrict__ out) {
    int warp = (blockIdx.x * blockDim.x + threadIdx.x) >> 5;
    int lane = threadIdx.x & 31;
    if (warp >= TT) return;
    int s = tei[warp];
    int t = tei[TT + warp];
    float2 a = reinterpret_cast<const float2*>(g_x + (size_t)s * DD)[lane];
    float2 b = reinterpret_cast<const float2*>(g_x + (size_t)t * DD)[lane];
    float p = a.x * b.x + a.y * b.y;
#pragma unroll
    for (int o = 16; o; o >>= 1) p += __shfl_xor_sync(0xffffffffu, p, o);
    if (lane == 0) out[warp] = p;
}

extern "C" void kernel_launch(void* const* d_in, const int* in_sizes, int n_in,
                              void* d_out, int out_size) {
    const int*   x_idx = (const int*)d_in[0];
    const int*   ei    = (const int*)d_in[1];
    const int*   et    = (const int*)d_in[2];
    const int*   tei   = (const int*)d_in[3];
    const float* emb   = (const float*)d_in[4];
    const float* W     = (const float*)d_in[5];
    const float* root  = (const float*)d_in[6];
    const float* bias  = (const float*)d_in[7];
    float* out = (float*)d_out;

    cudaFuncSetAttribute(k_layer, cudaFuncAttributeMaxDynamicSharedMemorySize, SM2_TOTAL);

    void *p_hist2, *p_x, *p_x2, *p_wh, *p_wl, *p_rh, *p_rl;
    cudaGetSymbolAddress(&p_hist2, g_hist2);
    cudaGetSymbolAddress(&p_x, g_x);
    cudaGetSymbolAddress(&p_x2, g_x2);
    cudaGetSymbolAddress(&p_wh, g_wh);
    cudaGetSymbolAddress(&p_wl, g_wl);
    cudaGetSymbolAddress(&p_rh, g_rh);
    cudaGetSymbolAddress(&p_rl, g_rl);
    float* px  = (float*)p_x;
    float* px2 = (float*)p_x2;
    const __nv_bfloat16* wh = (const __nv_bfloat16*)p_wh;
    const __nv_bfloat16* wl = (const __nv_bfloat16*)p_wl;
    const __nv_bfloat16* rh = (const __nv_bfloat16*)p_rh;
    const __nv_bfloat16* rl = (const __nv_bfloat16*)p_rl;

    cudaMemsetAsync(p_hist2, 0, RN * sizeof(int), 0);
    k_init_x<<<(NN * 16 + 255) / 256, 256>>>(x_idx, emb);
    int prep_n = 2 * RR * DD * DD + 2 * DD * DD;
    k_prep_w<<<(prep_n + 255) / 256, 256>>>(W, root);
    k_hist2<<<(EE + 255) / 256, 256>>>(ei, et);
    k_scan1<<<S2_BLKS, 1024>>>();
    k_scan2<<<1, 1024>>>();
    k_scan3<<<S2_BLKS, 1024>>>();
    k_invdeg2<<<(NN + 255) / 256, 256>>>();
    k_scatter2<<<(EE + 255) / 256, 256>>>(ei, et);

    int ltiles = (NN + 127) / 128;  // 782
    for (int l = 0; l < 2; l++) {
        const float* xi = (l == 0) ? px : px2;
        float*       xo = (l == 0) ? px2 : px;
        k_layer<<<ltiles, 256, SM2_TOTAL>>>(
            xi, xo,
            wh + (size_t)l * RR * DD * DD, wl + (size_t)l * RR * DD * DD,
            rh + (size_t)l * DD * DD, rl + (size_t)l * DD * DD,
            bias + (size_t)l * DD);
    }
    k_score<<<(TT * 32 + 255) / 256, 256>>>(tei, out);
}

// round 12
// speedup vs baseline: 1.5857x; 1.5857x over previous
#include <cuda_runtime.h>
#include <cuda_bf16.h>
#include <cuda_fp16.h>
#include <cstdint>

#define NN 100000
#define EE 1280000
#define RR 8
#define DD 64
#define TT 50000
#define SCAN_BLKS ((NN + 1023) / 1024)   // 98

// ---- scratch (device globals: alloc-free rule) ----
__device__ float g_x[(size_t)NN * DD];        // fp32 x (for score)
__device__ __half g_h[(size_t)RR * NN * DD];  // 102.4 MB (L2-resident!)
__device__ float g_agg[(size_t)NN * DD];      // pre-scaled mean aggregate
__device__ __nv_bfloat16 g_xh[(size_t)NN * DD];
__device__ __nv_bfloat16 g_xl[(size_t)NN * DD];
__device__ __nv_bfloat16 g_wh[2 * RR * DD * DD];  // W^T hi  [l][r][n][k]
__device__ __nv_bfloat16 g_wl[2 * RR * DD * DD];
__device__ __nv_bfloat16 g_rh[2 * DD * DD];       // root^T hi [l][n][k]
__device__ __nv_bfloat16 g_rl[2 * DD * DD];
// CSR structures
__device__ int g_hist[NN];
__device__ int g_rs[NN + 1];
__device__ int g_cur[NN];
__device__ int g_bsum[SCAN_BLKS];
__device__ int g_boff[SCAN_BLKS];
__device__ uint32_t g_eg[EE];   // packed: src | (r<<20)

__device__ __forceinline__ uint32_t smem_u32(const void* p) {
    uint32_t a;
    asm("{ .reg .u64 t; cvta.to.shared.u64 t, %1; cvt.u32.u64 %0, t; }" : "=r"(a) : "l"(p));
    return a;
}

#define LDM_X4(r, addr)                                                          \
    asm volatile("ldmatrix.sync.aligned.m8n8.x4.shared.b16 {%0,%1,%2,%3}, [%4];" \
        : "=r"((r)[0]), "=r"((r)[1]), "=r"((r)[2]), "=r"((r)[3]) : "r"(addr))

#define LDM_X2(r, addr)                                                          \
    asm volatile("ldmatrix.sync.aligned.m8n8.x2.shared.b16 {%0,%1}, [%2];"       \
        : "=r"((r)[0]), "=r"((r)[1]) : "r"(addr))

#define MMA_BF16(c, a, b)                                                        \
    asm volatile("mma.sync.aligned.m16n8k16.row.col.f32.bf16.bf16.f32 "          \
        "{%0,%1,%2,%3}, {%4,%5,%6,%7}, {%8,%9}, {%0,%1,%2,%3};"                  \
        : "+f"((c)[0]), "+f"((c)[1]), "+f"((c)[2]), "+f"((c)[3])                 \
        : "r"((a)[0]), "r"((a)[1]), "r"((a)[2]), "r"((a)[3]),                    \
          "r"((b)[0]), "r"((b)[1]))

__device__ __forceinline__ void split_store(float v, __nv_bfloat16* hi, __nv_bfloat16* lo) {
    __nv_bfloat16 h = __float2bfloat16(v);
    *hi = h;
    *lo = __float2bfloat16(v - __bfloat162float(h));
}

// ---- init: x = node_emb[x_idx] (+ bf16 split) ----
__global__ void k_init_x(const int* __restrict__ x_idx, const float* __restrict__ emb) {
    int i = blockIdx.x * blockDim.x + threadIdx.x;
    if (i >= NN * (DD / 4)) return;
    int n = i >> 4, c = i & 15;
    int s = x_idx[n];
    float4 v = reinterpret_cast<const float4*>(emb)[(size_t)s * 16 + c];
    reinterpret_cast<float4*>(g_x)[(size_t)n * 16 + c] = v;
    size_t e = (size_t)n * DD + c * 4;
    split_store(v.x, &g_xh[e + 0], &g_xl[e + 0]);
    split_store(v.y, &g_xh[e + 1], &g_xl[e + 1]);
    split_store(v.z, &g_xh[e + 2], &g_xl[e + 2]);
    split_store(v.w, &g_xh[e + 3], &g_xl[e + 3]);
}

// ---- prep: transpose + split W (both layers) and root ----
__global__ void k_prep_w(const float* __restrict__ W, const float* __restrict__ root) {
    int idx = blockIdx.x * blockDim.x + threadIdx.x;
    int nW = 2 * RR * DD * DD;
    if (idx < nW) {
        int k = idx & 63, n = (idx >> 6) & 63, r = (idx >> 12) & 7, l = idx >> 15;
        float v = W[(((size_t)l * RR + r) * DD + k) * DD + n];
        split_store(v, &g_wh[idx], &g_wl[idx]);
    } else if (idx < nW + 2 * DD * DD) {
        int o = idx - nW;
        int k = o & 63, n = (o >> 6) & 63, l = o >> 12;
        float v = root[((size_t)l * DD + k) * DD + n];
        split_store(v, &g_rh[o], &g_rl[o]);
    }
}

// ---- CSR build ----
__global__ void k_hist(const int* __restrict__ ei) {
    int e = blockIdx.x * blockDim.x + threadIdx.x;
    if (e < EE) atomicAdd(&g_hist[ei[EE + e]], 1);
}

__global__ __launch_bounds__(1024) void k_scan1() {
    __shared__ int sh[1024];
    int tid = threadIdx.x;
    int i = blockIdx.x * 1024 + tid;
    int v = (i < NN) ? g_hist[i] : 0;
    sh[tid] = v;
    __syncthreads();
    for (int off = 1; off < 1024; off <<= 1) {
        int t = (tid >= off) ? sh[tid - off] : 0;
        __syncthreads();
        sh[tid] += t;
        __syncthreads();
    }
    if (i < NN) g_rs[i] = sh[tid] - v;
    if (tid == 1023) g_bsum[blockIdx.x] = sh[1023];
}

__global__ __launch_bounds__(128) void k_scan2() {
    __shared__ int sh[128];
    int tid = threadIdx.x;
    int v = (tid < SCAN_BLKS) ? g_bsum[tid] : 0;
    sh[tid] = v;
    __syncthreads();
    for (int off = 1; off < 128; off <<= 1) {
        int t = (tid >= off) ? sh[tid - off] : 0;
        __syncthreads();
        sh[tid] += t;
        __syncthreads();
    }
    if (tid < SCAN_BLKS) g_boff[tid] = sh[tid] - v;
}

__global__ __launch_bounds__(1024) void k_scan3() {
    int i = blockIdx.x * 1024 + threadIdx.x;
    if (i < NN) {
        int rs = g_rs[i] + g_boff[blockIdx.x];
        g_rs[i] = rs;
        g_cur[i] = rs;
    }
    if (i == 0) g_rs[NN] = EE;
}

__global__ void k_scatter(const int* __restrict__ ei, const int* __restrict__ et) {
    int e = blockIdx.x * blockDim.x + threadIdx.x;
    if (e >= EE) return;
    int dst = ei[EE + e];
    int pos = atomicAdd(&g_cur[dst], 1);
    g_eg[pos] = (uint32_t)ei[e] | ((uint32_t)et[e] << 20);
}

// ================= HMMA split GEMM: h[r] = x @ W[r] (fp16 out) =================
#define PAD 72
#define A_BYTES (128 * PAD * 2)
#define W_BYTES (64 * PAD * 2)
#define SM_AH 0
#define SM_AL A_BYTES
#define SM_WH (2 * A_BYTES)
#define SM_WL (2 * A_BYTES + W_BYTES)
#define SM_TOTAL (2 * A_BYTES + 2 * W_BYTES)

__global__ __launch_bounds__(256)
void k_gemm_h_tc(const __nv_bfloat16* __restrict__ wh,
                 const __nv_bfloat16* __restrict__ wl) {
    extern __shared__ __align__(16) char sm[];
    int tid = threadIdx.x;
    int n0 = blockIdx.x * 128;
    int r  = blockIdx.y;

    const uint4 z4 = make_uint4(0, 0, 0, 0);
    for (int i = tid; i < 128 * 8; i += 256) {
        int row = i >> 3, c = i & 7;
        uint4 vh = z4, vl = z4;
        if (n0 + row < NN) {
            size_t g = (size_t)(n0 + row) * 8 + c;
            vh = reinterpret_cast<const uint4*>(g_xh)[g];
            vl = reinterpret_cast<const uint4*>(g_xl)[g];
        }
        *reinterpret_cast<uint4*>(sm + SM_AH + row * 144 + c * 16) = vh;
        *reinterpret_cast<uint4*>(sm + SM_AL + row * 144 + c * 16) = vl;
    }
    for (int i = tid; i < 64 * 8; i += 256) {
        int row = i >> 3, c = i & 7;
        size_t g = (size_t)r * 512 + (size_t)row * 8 + c;
        *reinterpret_cast<uint4*>(sm + SM_WH + row * 144 + c * 16) =
            reinterpret_cast<const uint4*>(wh)[g];
        *reinterpret_cast<uint4*>(sm + SM_WL + row * 144 + c * 16) =
            reinterpret_cast<const uint4*>(wl)[g];
    }
    __syncthreads();

    uint32_t sb = smem_u32(sm);
    int w = tid >> 5, t = tid & 31;
    int tt = t & 15;
    float acc[8][4] = {};
    uint32_t a_row = w * 16 + (t & 15);
    uint32_t a_col_half = (t >> 4);
    uint32_t b_row = tt & 7;
    uint32_t b_half = (tt >> 3) & 1;

#pragma unroll
    for (int kb = 0; kb < 4; kb++) {
        uint32_t aoff = a_row * 144 + (kb * 16 + a_col_half * 8) * 2;
        uint32_t ah[4], al[4];
        LDM_X4(ah, sb + SM_AH + aoff);
        LDM_X4(al, sb + SM_AL + aoff);
#pragma unroll
        for (int nb = 0; nb < 8; nb++) {
            uint32_t boff = (nb * 8 + b_row) * 144 + (kb * 16 + b_half * 8) * 2;
            uint32_t bh[2], bl[2];
            LDM_X2(bh, sb + SM_WH + boff);
            LDM_X2(bl, sb + SM_WL + boff);
            MMA_BF16(acc[nb], ah, bh);
            MMA_BF16(acc[nb], ah, bl);
            MMA_BF16(acc[nb], al, bh);
        }
    }

    // epilogue: fp16 h
    int row0 = n0 + w * 16 + (t >> 2);
    int col2 = (t & 3) * 2;
    __half* hb = g_h + (size_t)r * NN * DD;
#pragma unroll
    for (int nb = 0; nb < 8; nb++) {
        int col = nb * 8 + col2;
        if (row0 < NN)
            *reinterpret_cast<__half2*>(hb + (size_t)row0 * DD + col) =
                __floats2half2_rn(acc[nb][0], acc[nb][1]);
        if (row0 + 8 < NN)
            *reinterpret_cast<__half2*>(hb + (size_t)(row0 + 8) * DD + col) =
                __floats2half2_rn(acc[nb][2], acc[nb][3]);
    }
}

// ---- edge aggregation: warp per dst via CSR; fp16 h gather, fp32 accum ----
__device__ __forceinline__ float2 h_row(uint32_t p, int lane) {
    int src = p & 0xFFFFF;
    int r = p >> 20;
    __half2 v = reinterpret_cast<const __half2*>(g_h + ((size_t)r * NN + src) * DD)[lane];
    return __half22float2(v);
}

__global__ __launch_bounds__(256) void k_edge_csr() {
    int d = (blockIdx.x * blockDim.x + threadIdx.x) >> 5;
    int lane = threadIdx.x & 31;
    if (d >= NN) return;
    int beg = g_rs[d], end = g_rs[d + 1];
    int deg = end - beg;
    float2 acc = make_float2(0.f, 0.f);
    int e = beg;
    while (e < end) {
        int cnt = min(32, end - e);
        uint32_t pk = (lane < cnt) ? g_eg[e + lane] : 0u;
        int j = 0;
        for (; j + 4 <= cnt; j += 4) {
            uint32_t p0 = __shfl_sync(0xffffffffu, pk, j);
            uint32_t p1 = __shfl_sync(0xffffffffu, pk, j + 1);
            uint32_t p2 = __shfl_sync(0xffffffffu, pk, j + 2);
            uint32_t p3 = __shfl_sync(0xffffffffu, pk, j + 3);
            float2 v0 = h_row(p0, lane);
            float2 v1 = h_row(p1, lane);
            float2 v2 = h_row(p2, lane);
            float2 v3 = h_row(p3, lane);
            acc.x += (v0.x + v1.x) + (v2.x + v3.x);
            acc.y += (v0.y + v1.y) + (v2.y + v3.y);
        }
        for (; j < cnt; j++) {
            uint32_t p = __shfl_sync(0xffffffffu, pk, j);
            float2 v = h_row(p, lane);
            acc.x += v.x;
            acc.y += v.y;
        }
        e += cnt;
    }
    float sc = 1.0f / fmaxf((float)deg, 1.0f);
    reinterpret_cast<float2*>(g_agg + (size_t)d * DD)[lane] =
        make_float2(acc.x * sc, acc.y * sc);
}

// ---- update (HMMA): x = relu(agg + x @ root + bias); writes x + splits in place ----
__global__ __launch_bounds__(256)
void k_update_tc(const __nv_bfloat16* __restrict__ rh,
                 const __nv_bfloat16* __restrict__ rl,
                 const float* __restrict__ bias) {
    extern __shared__ __align__(16) char sm[];
    int tid = threadIdx.x;
    int n0 = blockIdx.x * 128;

    const uint4 z4 = make_uint4(0, 0, 0, 0);
    for (int i = tid; i < 128 * 8; i += 256) {
        int row = i >> 3, c = i & 7;
        uint4 vh = z4, vl = z4;
        if (n0 + row < NN) {
            size_t g = (size_t)(n0 + row) * 8 + c;
            vh = reinterpret_cast<const uint4*>(g_xh)[g];
            vl = reinterpret_cast<const uint4*>(g_xl)[g];
        }
        *reinterpret_cast<uint4*>(sm + SM_AH + row * 144 + c * 16) = vh;
        *reinterpret_cast<uint4*>(sm + SM_AL + row * 144 + c * 16) = vl;
    }
    for (int i = tid; i < 64 * 8; i += 256) {
        int row = i >> 3, c = i & 7;
        size_t g = (size_t)row * 8 + c;
        *reinterpret_cast<uint4*>(sm + SM_WH + row * 144 + c * 16) =
            reinterpret_cast<const uint4*>(rh)[g];
        *reinterpret_cast<uint4*>(sm + SM_WL + row * 144 + c * 16) =
            reinterpret_cast<const uint4*>(rl)[g];
    }
    __syncthreads();

    uint32_t sb = smem_u32(sm);
    int w = tid >> 5, t = tid & 31;
    int tt = t & 15;
    float acc[8][4] = {};
    uint32_t a_row = w * 16 + (t & 15);
    uint32_t a_col_half = (t >> 4);
    uint32_t b_row = tt & 7;
    uint32_t b_half = (tt >> 3) & 1;

#pragma unroll
    for (int kb = 0; kb < 4; kb++) {
        uint32_t aoff = a_row * 144 + (kb * 16 + a_col_half * 8) * 2;
        uint32_t ah[4], al[4];
        LDM_X4(ah, sb + SM_AH + aoff);
        LDM_X4(al, sb + SM_AL + aoff);
#pragma unroll
        for (int nb = 0; nb < 8; nb++) {
            uint32_t boff = (nb * 8 + b_row) * 144 + (kb * 16 + b_half * 8) * 2;
            uint32_t bh[2], bl[2];
            LDM_X2(bh, sb + SM_WH + boff);
            LDM_X2(bl, sb + SM_WL + boff);
            MMA_BF16(acc[nb], ah, bh);
            MMA_BF16(acc[nb], ah, bl);
            MMA_BF16(acc[nb], al, bh);
        }
    }

    int row0 = n0 + w * 16 + (t >> 2);
    int col2 = (t & 3) * 2;
#pragma unroll
    for (int nb = 0; nb < 8; nb++) {
        int col = nb * 8 + col2;
        float2 bs = *reinterpret_cast<const float2*>(bias + col);
#pragma unroll
        for (int rr2 = 0; rr2 < 2; rr2++) {
            int row = row0 + rr2 * 8;
            if (row < NN) {
                float2 ag = *reinterpret_cast<const float2*>(g_agg + (size_t)row * DD + col);
                float ox = fmaxf(acc[nb][rr2 * 2 + 0] + ag.x + bs.x, 0.f);
                float oy = fmaxf(acc[nb][rr2 * 2 + 1] + ag.y + bs.y, 0.f);
                *reinterpret_cast<float2*>(g_x + (size_t)row * DD + col) = make_float2(ox, oy);
                __nv_bfloat16 hx = __float2bfloat16(ox);
                __nv_bfloat16 hy = __float2bfloat16(oy);
                __nv_bfloat162 hh;  hh.x = hx;  hh.y = hy;
                __nv_bfloat162 ll;
                ll.x = __float2bfloat16(ox - __bfloat162float(hx));
                ll.y = __float2bfloat16(oy - __bfloat162float(hy));
                *reinterpret_cast<__nv_bfloat162*>(&g_xh[(size_t)row * DD + col]) = hh;
                *reinterpret_cast<__nv_bfloat162*>(&g_xl[(size_t)row * DD + col]) = ll;
            }
        }
    }
}

// ---- final: out[t] = dot(x[s_t], x[t_t]) ; warp per target ----
__global__ void k_score(const int* __restrict__ tei, float* __restrict__ out) {
    int warp = (blockIdx.x * blockDim.x + threadIdx.x) >> 5;
    int lane = threadIdx.x & 31;
    if (warp >= TT) return;
    int s = tei[warp];
    int t = tei[TT + warp];
    float2 a = reinterpret_cast<const float2*>(g_x + (size_t)s * DD)[lane];
    float2 b = reinterpret_cast<const float2*>(g_x + (size_t)t * DD)[lane];
    float p = a.x * b.x + a.y * b.y;
#pragma unroll
    for (int o = 16; o; o >>= 1) p += __shfl_xor_sync(0xffffffffu, p, o);
    if (lane == 0) out[warp] = p;
}

extern "C" void kernel_launch(void* const* d_in, const int* in_sizes, int n_in,
                              void* d_out, int out_size) {
    const int*   x_idx = (const int*)d_in[0];
    const int*   ei    = (const int*)d_in[1];
    const int*   et    = (const int*)d_in[2];
    const int*   tei   = (const int*)d_in[3];
    const float* emb   = (const float*)d_in[4];
    const float* W     = (const float*)d_in[5];
    const float* root  = (const float*)d_in[6];
    const float* bias  = (const float*)d_in[7];
    float* out = (float*)d_out;

    cudaFuncSetAttribute(k_gemm_h_tc, cudaFuncAttributeMaxDynamicSharedMemorySize, SM_TOTAL);
    cudaFuncSetAttribute(k_update_tc, cudaFuncAttributeMaxDynamicSharedMemorySize, SM_TOTAL);

    void *p_hist, *p_wh, *p_wl, *p_rh, *p_rl;
    cudaGetSymbolAddress(&p_hist, g_hist);
    cudaGetSymbolAddress(&p_wh, g_wh);
    cudaGetSymbolAddress(&p_wl, g_wl);
    cudaGetSymbolAddress(&p_rh, g_rh);
    cudaGetSymbolAddress(&p_rl, g_rl);
    const __nv_bfloat16* wh = (const __nv_bfloat16*)p_wh;
    const __nv_bfloat16* wl = (const __nv_bfloat16*)p_wl;
    const __nv_bfloat16* rh = (const __nv_bfloat16*)p_rh;
    const __nv_bfloat16* rl = (const __nv_bfloat16*)p_rl;

    cudaMemsetAsync(p_hist, 0, NN * sizeof(int), 0);
    k_init_x<<<(NN * 16 + 255) / 256, 256>>>(x_idx, emb);
    int prep_n = 2 * RR * DD * DD + 2 * DD * DD;
    k_prep_w<<<(prep_n + 255) / 256, 256>>>(W, root);
    k_hist<<<(EE + 255) / 256, 256>>>(ei);
    k_scan1<<<SCAN_BLKS, 1024>>>();
    k_scan2<<<1, 128>>>();
    k_scan3<<<SCAN_BLKS, 1024>>>();
    k_scatter<<<(EE + 255) / 256, 256>>>(ei, et);

    int htiles = (NN + 127) / 128;  // 782
    int eblocks = (NN * 32 + 255) / 256;  // 12500
    for (int l = 0; l < 2; l++) {
        k_gemm_h_tc<<<dim3(htiles, RR), 256, SM_TOTAL>>>(
            wh + (size_t)l * RR * DD * DD, wl + (size_t)l * RR * DD * DD);
        k_edge_csr<<<eblocks, 256>>>();
        k_update_tc<<<htiles, 256, SM_TOTAL>>>(rh + (size_t)l * DD * DD,
                                               rl + (size_t)l * DD * DD,
                                               bias + (size_t)l * DD);
    }
    k_score<<<(TT * 32 + 255) / 256, 256>>>(tei, out);
}